// round 16
// baseline (speedup 1.0000x reference)
#include <cuda_runtime.h>
#include <cuda_bf16.h>
#include <cstdint>

// Problem constants
#define N_ROWS 16384
#define SPLIT  100
#define IDIM   128
#define NH     4
#define PD     64
#define OUTD   (NH * PD)        // 256
#define MITERS (SPLIT / 2)      // 50 iters, 1KB (2 segments) each
#define SLOTS  4                // ring slots of 1KB each (4KB/warp)
#define PRE    3                // groups in flight (3KB/warp outstanding)
#define NWARP  4                // warps (rows) per block

// wq[h][i] = sum_o W[h,i,o] * q[h,o]  — precomputed by a tiny kernel
__device__ float g_wq[NH * IDIM];

__global__ void wq_kernel(const float* __restrict__ W, const float* __restrict__ q) {
    int idx = threadIdx.x;                     // 512 threads
    if (idx >= NH * IDIM) return;
    int h = idx >> 7, i = idx & 127;
    const float* Wr = W + ((size_t)(h * IDIM + i)) * PD;
    const float* qr = q + h * PD;
    float acc = 0.f;
#pragma unroll
    for (int o = 0; o < PD; o++) acc = fmaf(Wr[o], qr[o], acc);
    g_wq[idx] = acc;
}

__device__ __forceinline__ void cp16(void* smem_dst, const void* gsrc) {
    unsigned saddr = (unsigned)__cvta_generic_to_shared(smem_dst);
    asm volatile("cp.async.cg.shared.global [%0], [%1], 16;\n" :: "r"(saddr), "l"(gsrc));
}
__device__ __forceinline__ void cp_commit() { asm volatile("cp.async.commit_group;\n"); }
__device__ __forceinline__ void cp_wait_pre() { asm volatile("cp.async.wait_group %0;\n" :: "n"(PRE - 1)); }

// ---- packed fp32x2 helpers (Blackwell FFMA2 — only reachable via PTX) ----
#define FMA2(d, a, b, c) \
    asm("fma.rn.f32x2 %0, %1, %2, %3;" : "=l"(d) : "l"(a), "l"(b), "l"(c))
__device__ __forceinline__ unsigned long long pk(float lo, float hi) {
    unsigned long long r;
    asm("mov.b64 %0, {%1, %2};" : "=l"(r) : "f"(lo), "f"(hi));
    return r;
}
__device__ __forceinline__ unsigned long long pack2(float v) {
    unsigned long long r;
    asm("mov.b64 %0, {%1, %1};" : "=l"(r) : "f"(v));
    return r;
}
__device__ __forceinline__ float2 unpk(unsigned long long v) {
    float lo, hi;
    asm("mov.b64 {%0, %1}, %2;" : "=f"(lo), "=f"(hi) : "l"(v));
    return make_float2(lo, hi);
}
__device__ __forceinline__ float hadd2(unsigned long long v) {
    float2 p = unpk(v);
    return p.x + p.y;
}

__global__ void __launch_bounds__(NWARP * 32, 8)
attn_kernel(const float* __restrict__ x, const float* __restrict__ W,
            float* __restrict__ out) {
    // per-warp ring: SLOTS slots of 2 segments (256 floats = 64 float4 = 1KB)
    __shared__ float4 ring[NWARP][SLOTS][64];    // 16 KB
    __shared__ float sdsum[NWARP][NH];           // per-row softmax denominators

    const int warp = threadIdx.x >> 5;
    const int lane = threadIdx.x & 31;
    const int half = lane >> 4;                 // head-pair owner: heads {2*half, 2*half+1}
    const int p16  = lane & 15;                 // owns i in [p16*8, p16*8+8) of BOTH segments
    const int b3   = (p16 >> 3) & 1;            // head selector within the pair
    const int b2   = (p16 >> 2) & 1;            // segment selector (A/B)
    const int row  = blockIdx.x * NWARP + warp; // grid sized exactly: always < N_ROWS
    const float* xrow = x + (size_t)row * (SPLIT * IDIM);
    float4 (*slotp)[64] = ring[warp];

    // wq fragment: this lane's 8 i-values for its 2 heads, packed as 4 u64 pairs each
    unsigned long long wA[4], wB[4];
    {
        const float4* ga = (const float4*)(g_wq + (2 * half) * IDIM + p16 * 8);
        const float4* gb = (const float4*)(g_wq + (2 * half + 1) * IDIM + p16 * 8);
        float4 a0 = ga[0], a1 = ga[1], b0 = gb[0], b1 = gb[1];
        wA[0] = pk(a0.x, a0.y); wA[1] = pk(a0.z, a0.w);
        wA[2] = pk(a1.x, a1.y); wA[3] = pk(a1.z, a1.w);
        wB[0] = pk(b0.x, b0.y); wB[1] = pk(b0.z, b0.w);
        wB[2] = pk(b1.x, b1.y); wB[3] = pk(b1.z, b1.w);
    }

    // accumulators: 2 heads x 4 f32x2 pairs (16 regs) + 2 denominators
    unsigned long long h0[4] = {0ull, 0ull, 0ull, 0ull};
    unsigned long long h1[4] = {0ull, 0ull, 0ull, 0ull};
    float ds0 = 0.f, ds1 = 0.f;

    // prologue: fill PRE pipeline stages (lane copies float4[lane*2], [lane*2+1])
#pragma unroll
    for (int t = 0; t < PRE; t++) {
        const float* src = xrow + t * 256 + lane * 8;
        cp16(&slotp[t][lane * 2],     src);
        cp16(&slotp[t][lane * 2 + 1], src + 4);
        cp_commit();
    }

    for (int t = 0; t < MITERS; t++) {
        cp_wait_pre();
        __syncwarp();    // lanes read bytes cp'd by OTHER lanes (both halves read both segs)

        const int slot = t & (SLOTS - 1);
        // LDS.128 loads (float4 — guaranteed vector form), then pack to u64 pairs.
        // For a vector-loaded quad the pair-movs usually collapse to register aliases.
        float4 fa0 = slotp[slot][p16 * 2];
        float4 fa1 = slotp[slot][p16 * 2 + 1];
        float4 fb0 = slotp[slot][32 + p16 * 2];
        float4 fb1 = slotp[slot][32 + p16 * 2 + 1];

        // issue next stage; commit UNCONDITIONALLY (wait_group is commit-order keyed)
        const int nt = t + PRE;
        if (nt < MITERS) {
            const int ns = nt & (SLOTS - 1);
            const float* src = xrow + nt * 256 + lane * 8;
            cp16(&slotp[ns][lane * 2],     src);
            cp16(&slotp[ns][lane * 2 + 1], src + 4);
        }
        cp_commit();

        unsigned long long xA[4], xB[4];
        xA[0] = pk(fa0.x, fa0.y); xA[1] = pk(fa0.z, fa0.w);
        xA[2] = pk(fa1.x, fa1.y); xA[3] = pk(fa1.z, fa1.w);
        xB[0] = pk(fb0.x, fb0.y); xB[1] = pk(fb0.z, fb0.w);
        xB[2] = pk(fb1.x, fb1.y); xB[3] = pk(fb1.z, fb1.w);

        // partial scores: 2 heads x 2 segments over this lane's 8 i's (FFMA2 chains)
        float pA0, pA1, pB0, pB1;
        {
            unsigned long long a;
            a = 0ull;
            FMA2(a, xA[0], wA[0], a); FMA2(a, xA[1], wA[1], a);
            FMA2(a, xA[2], wA[2], a); FMA2(a, xA[3], wA[3], a);
            pA0 = hadd2(a);
            a = 0ull;
            FMA2(a, xA[0], wB[0], a); FMA2(a, xA[1], wB[1], a);
            FMA2(a, xA[2], wB[2], a); FMA2(a, xA[3], wB[3], a);
            pA1 = hadd2(a);
            a = 0ull;
            FMA2(a, xB[0], wA[0], a); FMA2(a, xB[1], wA[1], a);
            FMA2(a, xB[2], wA[2], a); FMA2(a, xB[3], wA[3], a);
            pB0 = hadd2(a);
            a = 0ull;
            FMA2(a, xB[0], wB[0], a); FMA2(a, xB[1], wB[1], a);
            FMA2(a, xB[2], wB[2], a); FMA2(a, xB[3], wB[3], a);
            pB1 = hadd2(a);
        }

        // specialized butterfly within the 16-lane half (5 shfls)
        float s1 = b3 ? pA0 : pA1;
        float r1 = __shfl_xor_sync(0xffffffffu, s1, 8);
        float uA = (b3 ? pA1 : pA0) + r1;
        float s2 = b3 ? pB0 : pB1;
        float r2 = __shfl_xor_sync(0xffffffffu, s2, 8);
        float uB = (b3 ? pB1 : pB0) + r2;
        float s3 = b2 ? uA : uB;
        float r3 = __shfl_xor_sync(0xffffffffu, s3, 4);
        float v  = (b2 ? uB : uA) + r3;              // (head 2*half+b3, seg b2)
        v += __shfl_xor_sync(0xffffffffu, v, 2);
        v += __shfl_xor_sync(0xffffffffu, v, 1);

        // leaky_relu -> exp, ONE per lane (|score| <~ 15 << 88, fp32-safe)
        float e = __expf(fmaxf(v, 0.2f * v));

        // allgather within the half (3 shfls): lane needs its 2 heads x 2 segs
        float g1 = __shfl_xor_sync(0xffffffffu, e, 4);
        float eX = b2 ? g1 : e;     // (head 2*half+b3, seg A)
        float eY = b2 ? e  : g1;    // (head 2*half+b3, seg B)
        float g2 = __shfl_xor_sync(0xffffffffu, eX, 8);
        float g3 = __shfl_xor_sync(0xffffffffu, eY, 8);
        float eA0 = b3 ? g2 : eX;   // (head 2*half,   seg A)
        float eA1 = b3 ? eX : g2;   // (head 2*half+1, seg A)
        float eB0 = b3 ? g3 : eY;   // (head 2*half,   seg B)
        float eB1 = b3 ? eY : g3;   // (head 2*half+1, seg B)

        // accumulate with FFMA2: 2 heads x 4 pairs x 2 segments = 16 FFMA2
        ds0 += eA0 + eB0;
        ds1 += eA1 + eB1;
        {
            unsigned long long pA0e = pack2(eA0), pA1e = pack2(eA1);
            unsigned long long pB0e = pack2(eB0), pB1e = pack2(eB1);
#pragma unroll
            for (int j = 0; j < 4; j++) {
                FMA2(h0[j], pA0e, xA[j], h0[j]);
                FMA2(h1[j], pA1e, xA[j], h1[j]);
                FMA2(h0[j], pB0e, xB[j], h0[j]);
                FMA2(h1[j], pB1e, xB[j], h1[j]);
            }
        }
    }

    // ---- stage UNNORMALIZED accumulators for ALL rows into ring space ----
    // Row r's region aliases other warps' ring slots: full block barrier first.
    // Halves own disjoint heads, lanes own disjoint i — no combine needed.
    float* sx = (float*)&ring[0][0][0];   // row r at sx[r*512 + h*128 + i]
    __syncthreads();
    {
        float2 a0 = unpk(h0[0]), a1 = unpk(h0[1]), a2 = unpk(h0[2]), a3 = unpk(h0[3]);
        float2 b0 = unpk(h1[0]), b1 = unpk(h1[1]), b2v = unpk(h1[2]), b3v = unpk(h1[3]);
        float4* d0 = (float4*)(sx + warp * 512 + (2 * half) * IDIM + p16 * 8);
        d0[0] = make_float4(a0.x, a0.y, a1.x, a1.y);
        d0[1] = make_float4(a2.x, a2.y, a3.x, a3.y);
        float4* d1 = (float4*)(sx + warp * 512 + (2 * half + 1) * IDIM + p16 * 8);
        d1[0] = make_float4(b0.x, b0.y, b1.x, b1.y);
        d1[1] = make_float4(b2v.x, b2v.y, b3v.x, b3v.y);
    }
    if (p16 == 0) {
        sdsum[warp][2 * half]     = ds0;
        sdsum[warp][2 * half + 1] = ds1;
    }
    __syncthreads();

    // ---- cooperative epilogue (FFMA2): warp w = head w, lane owns 2 output
    //      cols; each W float2 load amortized across all 4 rows ----
    {
        const int hh = warp;              // head handled by this warp
        const int c0 = lane * 2;          // output columns c0, c0+1
        const float* Wp = W + ((size_t)hh * IDIM) * PD + c0;  // W[hh][i][c0], stride PD per i
        const float* sxh = sx + hh * IDIM;                    // + r*512 per row

        unsigned long long acc[NWARP];
#pragma unroll
        for (int r = 0; r < NWARP; r++) acc[r] = 0ull;

#pragma unroll 4
        for (int i = 0; i < IDIM; i++) {
            float2 wv = *(const float2*)(Wp + i * PD);         // shared by all 4 rows
            unsigned long long wvp = pk(wv.x, wv.y);
#pragma unroll
            for (int r = 0; r < NWARP; r++) {
                unsigned long long xv = pack2(sxh[r * 512 + i]);  // LDS broadcast + pack
                FMA2(acc[r], xv, wvp, acc[r]);
            }
        }

#pragma unroll
        for (int r = 0; r < NWARP; r++) {
            float inv = 1.0f / sdsum[r][hh];
            float2 a = unpk(acc[r]);
            int row_r = blockIdx.x * NWARP + r;
            float2* op = (float2*)(out + (size_t)row_r * OUTD + hh * PD + c0);
            *op = make_float2(a.x * inv, a.y * inv);
        }
    }
}

extern "C" void kernel_launch(void* const* d_in, const int* in_sizes, int n_in,
                              void* d_out, int out_size) {
    // inputs: x [N, 12800], W [4,128,64], q [4,64] — identify defensively by size
    const float* x = (const float*)d_in[0];
    const float* W = (const float*)d_in[1];
    const float* q = (const float*)d_in[2];
    for (int i = 0; i < n_in && i < 3; i++) {
        if (in_sizes[i] == N_ROWS * SPLIT * IDIM) x = (const float*)d_in[i];
        else if (in_sizes[i] == NH * IDIM * PD)   W = (const float*)d_in[i];
        else if (in_sizes[i] == NH * PD)          q = (const float*)d_in[i];
    }
    float* out = (float*)d_out;

    wq_kernel<<<1, 512>>>(W, q);
    attn_kernel<<<N_ROWS / NWARP, NWARP * 32>>>(x, W, out);
}

// round 17
// speedup vs baseline: 1.0443x; 1.0443x over previous
#include <cuda_runtime.h>
#include <cuda_bf16.h>

// Problem constants
#define N_ROWS 16384
#define SPLIT  100
#define IDIM   128
#define NH     4
#define PD     64
#define OUTD   (NH * PD)        // 256
#define MIT2   (SPLIT / 4)      // 25 iters, 2KB (4 segments) each
#define SLOTS  3                // ring slots of 2KB each (6KB/warp)
#define PRE    2                // 2KB groups in flight per warp
#define NWARP  4                // warps (rows) per block

// wq[h][i] = sum_o W[h,i,o] * q[h,o]  — precomputed by a tiny kernel
__device__ float g_wq[NH * IDIM];

__global__ void wq_kernel(const float* __restrict__ W, const float* __restrict__ q) {
    int idx = threadIdx.x;                     // 512 threads
    if (idx >= NH * IDIM) return;
    int h = idx >> 7, i = idx & 127;
    const float* Wr = W + ((size_t)(h * IDIM + i)) * PD;
    const float* qr = q + h * PD;
    float acc = 0.f;
#pragma unroll
    for (int o = 0; o < PD; o++) acc = fmaf(Wr[o], qr[o], acc);
    g_wq[idx] = acc;
}

__device__ __forceinline__ void cp16(void* smem_dst, const void* gsrc) {
    unsigned saddr = (unsigned)__cvta_generic_to_shared(smem_dst);
    asm volatile("cp.async.cg.shared.global [%0], [%1], 16;\n" :: "r"(saddr), "l"(gsrc));
}
__device__ __forceinline__ void cp_commit() { asm volatile("cp.async.commit_group;\n"); }
__device__ __forceinline__ void cp_wait_pre() { asm volatile("cp.async.wait_group %0;\n" :: "n"(PRE - 1)); }

__global__ void __launch_bounds__(NWARP * 32, 8)
attn_kernel(const float* __restrict__ x, const float* __restrict__ W,
            float* __restrict__ out) {
    // per-warp ring: SLOTS slots of 4 segments (512 floats = 128 float4 = 2KB)
    __shared__ float4 ring[NWARP][SLOTS][128];   // 24 KB
    __shared__ float sdsum[NWARP][NH];           // per-row softmax denominators

    const int warp = threadIdx.x >> 5;
    const int lane = threadIdx.x & 31;
    const int half = lane >> 4;                 // head-pair owner: heads {2*half, 2*half+1}
    const int p16  = lane & 15;                 // owns i in [p16*8, p16*8+8) of BOTH segments
    const int b3   = (p16 >> 3) & 1;            // head selector within the pair
    const int b2   = (p16 >> 2) & 1;            // segment selector (A/B)
    const int row  = blockIdx.x * NWARP + warp; // grid sized exactly: always < N_ROWS
    const float* xrow = x + (size_t)row * (SPLIT * IDIM);
    float4 (*slotp)[128] = ring[warp];

    // wq fragment: this lane's 8 i-values for its 2 heads (16 regs)
    float4 wqa0, wqa1, wqb0, wqb1;
    {
        const float4* ga = (const float4*)(g_wq + (2 * half) * IDIM + p16 * 8);
        const float4* gb = (const float4*)(g_wq + (2 * half + 1) * IDIM + p16 * 8);
        wqa0 = ga[0]; wqa1 = ga[1];
        wqb0 = gb[0]; wqb1 = gb[1];
    }

    // accumulators: 2 heads x 8 i (16 regs) + 2 denominators
    float4 xh0a, xh0b, xh1a, xh1b;
    xh0a = xh0b = xh1a = xh1b = make_float4(0.f, 0.f, 0.f, 0.f);
    float ds0 = 0.f, ds1 = 0.f;

    // prologue: fill PRE pipeline stages (2KB each; lane copies 4x16B)
#pragma unroll
    for (int t = 0; t < PRE; t++) {
        const float* src = xrow + t * 512 + lane * 8;
        cp16(&slotp[t][lane * 2],          src);
        cp16(&slotp[t][lane * 2 + 1],      src + 4);
        cp16(&slotp[t][64 + lane * 2],     src + 256);
        cp16(&slotp[t][64 + lane * 2 + 1], src + 260);
        cp_commit();
    }

    int rs = 0;            // read slot for iteration t (t mod 3)
    int ws = PRE;          // write slot for iteration t+PRE

    for (int t = 0; t < MIT2; t++) {
        cp_wait_pre();   // commits so far g0..g(t+1); wait(1) => g(t) complete
        __syncwarp();    // lanes read bytes cp'd by OTHER lanes

        // issue next 2KB group; commit UNCONDITIONALLY (wait_group is
        // commit-order keyed — tail needs empty groups to slide the window)
        const int nt = t + PRE;
        if (nt < MIT2) {
            const float* src = xrow + nt * 512 + lane * 8;
            cp16(&slotp[ws][lane * 2],          src);
            cp16(&slotp[ws][lane * 2 + 1],      src + 4);
            cp16(&slotp[ws][64 + lane * 2],     src + 256);
            cp16(&slotp[ws][64 + lane * 2 + 1], src + 260);
        }
        cp_commit();

#pragma unroll
        for (int sub = 0; sub < 2; sub++) {
            // segment A = float4[sub*64 .. +32), segment B = [sub*64+32 .. +64)
            float4 xa0  = slotp[rs][sub * 64 + p16 * 2];
            float4 xa1  = slotp[rs][sub * 64 + p16 * 2 + 1];
            float4 xb0v = slotp[rs][sub * 64 + 32 + p16 * 2];
            float4 xb1v = slotp[rs][sub * 64 + 32 + p16 * 2 + 1];

            // partial scores: 2 heads x 2 segments over this lane's 8 i's
            float pA0, pA1, pB0, pB1;
            {
                float a;
                a = xa0.x * wqa0.x;  a = fmaf(xa0.y, wqa0.y, a); a = fmaf(xa0.z, wqa0.z, a); a = fmaf(xa0.w, wqa0.w, a);
                a = fmaf(xa1.x, wqa1.x, a); a = fmaf(xa1.y, wqa1.y, a); a = fmaf(xa1.z, wqa1.z, a); a = fmaf(xa1.w, wqa1.w, a);
                pA0 = a;
                a = xa0.x * wqb0.x;  a = fmaf(xa0.y, wqb0.y, a); a = fmaf(xa0.z, wqb0.z, a); a = fmaf(xa0.w, wqb0.w, a);
                a = fmaf(xa1.x, wqb1.x, a); a = fmaf(xa1.y, wqb1.y, a); a = fmaf(xa1.z, wqb1.z, a); a = fmaf(xa1.w, wqb1.w, a);
                pA1 = a;
                a = xb0v.x * wqa0.x; a = fmaf(xb0v.y, wqa0.y, a); a = fmaf(xb0v.z, wqa0.z, a); a = fmaf(xb0v.w, wqa0.w, a);
                a = fmaf(xb1v.x, wqa1.x, a); a = fmaf(xb1v.y, wqa1.y, a); a = fmaf(xb1v.z, wqa1.z, a); a = fmaf(xb1v.w, wqa1.w, a);
                pB0 = a;
                a = xb0v.x * wqb0.x; a = fmaf(xb0v.y, wqb0.y, a); a = fmaf(xb0v.z, wqb0.z, a); a = fmaf(xb0v.w, wqb0.w, a);
                a = fmaf(xb1v.x, wqb1.x, a); a = fmaf(xb1v.y, wqb1.y, a); a = fmaf(xb1v.z, wqb1.z, a); a = fmaf(xb1v.w, wqb1.w, a);
                pB1 = a;
            }

            // specialized butterfly within the 16-lane half (5 shfls)
            float s1 = b3 ? pA0 : pA1;
            float r1 = __shfl_xor_sync(0xffffffffu, s1, 8);
            float uA = (b3 ? pA1 : pA0) + r1;
            float s2 = b3 ? pB0 : pB1;
            float r2 = __shfl_xor_sync(0xffffffffu, s2, 8);
            float uB = (b3 ? pB1 : pB0) + r2;
            float s3 = b2 ? uA : uB;
            float r3 = __shfl_xor_sync(0xffffffffu, s3, 4);
            float v  = (b2 ? uB : uA) + r3;              // (head 2*half+b3, seg b2)
            v += __shfl_xor_sync(0xffffffffu, v, 2);
            v += __shfl_xor_sync(0xffffffffu, v, 1);

            // leaky_relu -> exp, ONE per lane (|score| <~ 15 << 88, fp32-safe)
            float e = __expf(fmaxf(v, 0.2f * v));

            // allgather within the half (3 shfls): lane needs its 2 heads x 2 segs
            float g1 = __shfl_xor_sync(0xffffffffu, e, 4);
            float eX = b2 ? g1 : e;     // (head 2*half+b3, seg A)
            float eY = b2 ? e  : g1;    // (head 2*half+b3, seg B)
            float g2 = __shfl_xor_sync(0xffffffffu, eX, 8);
            float g3 = __shfl_xor_sync(0xffffffffu, eY, 8);
            float eA0 = b3 ? g2 : eX;   // (head 2*half,   seg A)
            float eA1 = b3 ? eX : g2;   // (head 2*half+1, seg A)
            float eB0 = b3 ? g3 : eY;   // (head 2*half,   seg B)
            float eB1 = b3 ? eY : g3;   // (head 2*half+1, seg B)

            // accumulate: 2 heads x 8 i x 2 segments
            ds0 += eA0 + eB0;
            ds1 += eA1 + eB1;
            xh0a.x = fmaf(eA0, xa0.x, xh0a.x); xh0a.y = fmaf(eA0, xa0.y, xh0a.y);
            xh0a.z = fmaf(eA0, xa0.z, xh0a.z); xh0a.w = fmaf(eA0, xa0.w, xh0a.w);
            xh0b.x = fmaf(eA0, xa1.x, xh0b.x); xh0b.y = fmaf(eA0, xa1.y, xh0b.y);
            xh0b.z = fmaf(eA0, xa1.z, xh0b.z); xh0b.w = fmaf(eA0, xa1.w, xh0b.w);
            xh1a.x = fmaf(eA1, xa0.x, xh1a.x); xh1a.y = fmaf(eA1, xa0.y, xh1a.y);
            xh1a.z = fmaf(eA1, xa0.z, xh1a.z); xh1a.w = fmaf(eA1, xa0.w, xh1a.w);
            xh1b.x = fmaf(eA1, xa1.x, xh1b.x); xh1b.y = fmaf(eA1, xa1.y, xh1b.y);
            xh1b.z = fmaf(eA1, xa1.z, xh1b.z); xh1b.w = fmaf(eA1, xa1.w, xh1b.w);

            xh0a.x = fmaf(eB0, xb0v.x, xh0a.x); xh0a.y = fmaf(eB0, xb0v.y, xh0a.y);
            xh0a.z = fmaf(eB0, xb0v.z, xh0a.z); xh0a.w = fmaf(eB0, xb0v.w, xh0a.w);
            xh0b.x = fmaf(eB0, xb1v.x, xh0b.x); xh0b.y = fmaf(eB0, xb1v.y, xh0b.y);
            xh0b.z = fmaf(eB0, xb1v.z, xh0b.z); xh0b.w = fmaf(eB0, xb1v.w, xh0b.w);
            xh1a.x = fmaf(eB1, xb0v.x, xh1a.x); xh1a.y = fmaf(eB1, xb0v.y, xh1a.y);
            xh1a.z = fmaf(eB1, xb0v.z, xh1a.z); xh1a.w = fmaf(eB1, xb0v.w, xh1a.w);
            xh1b.x = fmaf(eB1, xb1v.x, xh1b.x); xh1b.y = fmaf(eB1, xb1v.y, xh1b.y);
            xh1b.z = fmaf(eB1, xb1v.z, xh1b.z); xh1b.w = fmaf(eB1, xb1v.w, xh1b.w);
        }

        rs = (rs == SLOTS - 1) ? 0 : rs + 1;
        ws = (ws == SLOTS - 1) ? 0 : ws + 1;
    }

    // ---- stage UNNORMALIZED accumulators for ALL rows into ring space ----
    // Row r's region aliases other warps' ring slots: full block barrier first.
    // Halves own disjoint heads, lanes own disjoint i — no combine needed.
    float* sx = (float*)&ring[0][0][0];   // row r at sx[r*512 + h*128 + i]
    __syncthreads();
    {
        float4* d0 = (float4*)(sx + warp * 512 + (2 * half) * IDIM + p16 * 8);
        d0[0] = xh0a;
        d0[1] = xh0b;
        float4* d1 = (float4*)(sx + warp * 512 + (2 * half + 1) * IDIM + p16 * 8);
        d1[0] = xh1a;
        d1[1] = xh1b;
    }
    if (p16 == 0) {
        sdsum[warp][2 * half]     = ds0;
        sdsum[warp][2 * half + 1] = ds1;
    }
    __syncthreads();

    // ---- cooperative epilogue: warp w = head w, lane owns 2 output cols,
    //      each W float2 load amortized across all 4 rows (8 FMAs/load) ----
    {
        const int hh = warp;              // head handled by this warp
        const int c0 = lane * 2;          // output columns c0, c0+1
        const float* Wp = W + ((size_t)hh * IDIM) * PD + c0;  // W[hh][i][c0], stride PD per i
        const float* sxh = sx + hh * IDIM;                    // + r*512 per row

        float2 acc[NWARP];
#pragma unroll
        for (int r = 0; r < NWARP; r++) acc[r] = make_float2(0.f, 0.f);

#pragma unroll 4
        for (int i = 0; i < IDIM; i++) {
            float2 wv = *(const float2*)(Wp + i * PD);         // shared by all 4 rows
#pragma unroll
            for (int r = 0; r < NWARP; r++) {
                float xv = sxh[r * 512 + i];                   // LDS broadcast
                acc[r].x = fmaf(xv, wv.x, acc[r].x);
                acc[r].y = fmaf(xv, wv.y, acc[r].y);
            }
        }

#pragma unroll
        for (int r = 0; r < NWARP; r++) {
            float inv = 1.0f / sdsum[r][hh];
            int row_r = blockIdx.x * NWARP + r;
            float2* op = (float2*)(out + (size_t)row_r * OUTD + hh * PD + c0);
            *op = make_float2(acc[r].x * inv, acc[r].y * inv);
        }
    }
}

extern "C" void kernel_launch(void* const* d_in, const int* in_sizes, int n_in,
                              void* d_out, int out_size) {
    // inputs: x [N, 12800], W [4,128,64], q [4,64] — identify defensively by size
    const float* x = (const float*)d_in[0];
    const float* W = (const float*)d_in[1];
    const float* q = (const float*)d_in[2];
    for (int i = 0; i < n_in && i < 3; i++) {
        if (in_sizes[i] == N_ROWS * SPLIT * IDIM) x = (const float*)d_in[i];
        else if (in_sizes[i] == NH * IDIM * PD)   W = (const float*)d_in[i];
        else if (in_sizes[i] == NH * PD)          q = (const float*)d_in[i];
    }
    float* out = (float*)d_out;

    wq_kernel<<<1, 512>>>(W, q);
    attn_kernel<<<N_ROWS / NWARP, NWARP * 32>>>(x, W, out);
}